// round 16
// baseline (speedup 1.0000x reference)
#include <cuda_runtime.h>
#include <cuda_bf16.h>
#include <cuda_fp16.h>
#include <cstdint>

// Problem constants
#define SEQ   2048
#define BATCH 2
#define DIM   1024
#define NH    16
#define HD    64
#define MTOK  (SEQ * BATCH)   // 4096 tokens
#define NTOT  (MTOK * DIM)    // 4M elements
#define NW    (DIM * DIM)     // 1M weight elements

// Scratch (allocation-free rule: __device__ globals)
// input splits (fp16 2-term)
__device__ __half g_xqh[NTOT], g_xql[NTOT];
__device__ __half g_xkh[NTOT], g_xkl[NTOT];
__device__ __half g_xvh[NTOT], g_xvl[NTOT];
// weights: QKV single fp16; O bf16 2-term
__device__ __half g_w16q[NW], g_w16k[NW], g_w16v[NW];
__device__ __nv_bfloat16 g_woh[NW], g_wol[NW];
// projected Q (fp16 2-term), K (fp16 single), V (fp16 single, natural layout)
__device__ __half g_qh[NTOT], g_ql[NTOT];
__device__ __half g_k16[NTOT];
__device__ __half g_v16[NTOT];
// attention output (bf16 2-term, feeds O-proj 3-pass)
__device__ __nv_bfloat16 g_xh[NTOT], g_xl[NTOT];

// ===========================================================================
// Helpers (family-safe PTX: cp.async, mma.sync, ldmatrix(+trans), ex2.f16x2)
// ===========================================================================
__device__ __forceinline__ uint32_t sm_u32(const void* p) {
    return (uint32_t)__cvta_generic_to_shared(p);
}
__device__ __forceinline__ void cp_async16(uint32_t smem_addr, const void* gptr) {
    asm volatile("cp.async.cg.shared.global [%0], [%1], 16;" :: "r"(smem_addr), "l"(gptr) : "memory");
}
#define CP_COMMIT() asm volatile("cp.async.commit_group;" ::: "memory")
#define CP_WAIT1()  asm volatile("cp.async.wait_group 1;" ::: "memory")
#define CP_WAIT2()  asm volatile("cp.async.wait_group 2;" ::: "memory")

__device__ __forceinline__ void mma_bf16(float* c, const uint32_t* a, const uint32_t* b) {
    asm volatile(
        "mma.sync.aligned.m16n8k16.row.col.f32.bf16.bf16.f32 "
        "{%0,%1,%2,%3}, {%4,%5,%6,%7}, {%8,%9}, {%0,%1,%2,%3};"
        : "+f"(c[0]), "+f"(c[1]), "+f"(c[2]), "+f"(c[3])
        : "r"(a[0]), "r"(a[1]), "r"(a[2]), "r"(a[3]), "r"(b[0]), "r"(b[1]));
}
__device__ __forceinline__ void mma_f16(float* c, const uint32_t* a, const uint32_t* b) {
    asm volatile(
        "mma.sync.aligned.m16n8k16.row.col.f32.f16.f16.f32 "
        "{%0,%1,%2,%3}, {%4,%5,%6,%7}, {%8,%9}, {%0,%1,%2,%3};"
        : "+f"(c[0]), "+f"(c[1]), "+f"(c[2]), "+f"(c[3])
        : "r"(a[0]), "r"(a[1]), "r"(a[2]), "r"(a[3]), "r"(b[0]), "r"(b[1]));
}
__device__ __forceinline__ void ldsm_x4(uint32_t* r, uint32_t addr) {
    asm volatile("ldmatrix.sync.aligned.m8n8.x4.shared.b16 {%0,%1,%2,%3}, [%4];"
                 : "=r"(r[0]), "=r"(r[1]), "=r"(r[2]), "=r"(r[3]) : "r"(addr));
}
__device__ __forceinline__ void ldsm_x4_trans(uint32_t* r, uint32_t addr) {
    asm volatile("ldmatrix.sync.aligned.m8n8.x4.trans.shared.b16 {%0,%1,%2,%3}, [%4];"
                 : "=r"(r[0]), "=r"(r[1]), "=r"(r[2]), "=r"(r[3]) : "r"(addr));
}
__device__ __forceinline__ uint32_t exp2_f16x2(uint32_t x) {
    uint32_t r;
    asm("ex2.approx.f16x2 %0, %1;" : "=r"(r) : "r"(x));
    return r;
}

// bf16 2-term split pack
__device__ __forceinline__ void packsplit2(float x, float y, uint32_t& h, uint32_t& l) {
    __nv_bfloat162 hb = __float22bfloat162_rn(make_float2(x, y));
    h = *reinterpret_cast<uint32_t*>(&hb);
    float rx = x - __low2float(hb);
    float ry = y - __high2float(hb);
    __nv_bfloat162 lb = __float22bfloat162_rn(make_float2(rx, ry));
    l = *reinterpret_cast<uint32_t*>(&lb);
}
// fp16 2-term split pack
__device__ __forceinline__ void packsplit2h(float x, float y, uint32_t& h, uint32_t& l) {
    __half2 hb = __float22half2_rn(make_float2(x, y));
    h = *reinterpret_cast<uint32_t*>(&hb);
    float rx = x - __low2float(hb);
    float ry = y - __high2float(hb);
    __half2 lb = __float22half2_rn(make_float2(rx, ry));
    l = *reinterpret_cast<uint32_t*>(&lb);
}
__device__ __forceinline__ uint32_t packh2(float x, float y) {
    __half2 hp = __float22half2_rn(make_float2(x, y));
    return *reinterpret_cast<uint32_t*>(&hp);
}

// ===========================================================================
// Prep: merged split kernel
// ===========================================================================
__global__ __launch_bounds__(256)
void split_all_kernel(const float* __restrict__ q, const float* __restrict__ k,
                      const float* __restrict__ v,
                      const float* __restrict__ wq, const float* __restrict__ wk,
                      const float* __restrict__ wv, const float* __restrict__ wo)
{
    const int y = blockIdx.y;
    const int i4 = (blockIdx.x * 256 + threadIdx.x) * 4;
    if (y < 3) {
        const float* src = (y == 0) ? q : (y == 1) ? k : v;
        __half* h = (y == 0) ? g_xqh : (y == 1) ? g_xkh : g_xvh;
        __half* l = (y == 0) ? g_xql : (y == 1) ? g_xkl : g_xvl;
        float4 t = *(const float4*)(src + i4);
        uint32_t h0, l0, h1, l1;
        packsplit2h(t.x, t.y, h0, l0);
        packsplit2h(t.z, t.w, h1, l1);
        uint2 hh = {h0, h1}, ll = {l0, l1};
        *(uint2*)(h + i4) = hh;
        *(uint2*)(l + i4) = ll;
    } else if (y < 6) {
        if (i4 >= NW) return;
        const int w = y - 3;
        const float* src = (w == 0) ? wq : (w == 1) ? wk : wv;
        __half* h = (w == 0) ? g_w16q : (w == 1) ? g_w16k : g_w16v;
        float4 t = *(const float4*)(src + i4);
        uint2 hh = {packh2(t.x, t.y), packh2(t.z, t.w)};
        *(uint2*)(h + i4) = hh;
    } else {
        if (i4 >= NW) return;
        float4 t = *(const float4*)(wo + i4);
        uint32_t h0, l0, h1, l1;
        packsplit2(t.x, t.y, h0, l0);
        packsplit2(t.z, t.w, h1, l1);
        uint2 hh = {h0, h1}, ll = {l0, l1};
        *(uint2*)(g_woh + i4) = hh;
        *(uint2*)(g_wol + i4) = ll;
    }
}

// ===========================================================================
// fp16 2-pass GEMM: Y = (Xh+Xl)@W16^T + bias
// CTA 128x128, 128 THREADS (4 warps, 64x64 each, 256 regs), K-chunk 32,
// 2-stage, pitch-80 rows. Modes: 1 = fp16 h/l out, 2 = fp16 single out.
// ===========================================================================
#define G2_PITCH 80
#define G2_ARR   (128 * G2_PITCH)       // 10240
#define G2_STAGE (3 * G2_ARR)           // 30720: Xh, Xl, W
#define G2_DSMEM (2 * G2_STAGE)         // 61440 -> 2 CTAs/SM

__device__ __forceinline__ void gemm2_core(
    const __half* __restrict__ Xh, const __half* __restrict__ Xl,
    const __half* __restrict__ W, const float* __restrict__ bias,
    __half* __restrict__ Yh, __half* __restrict__ Yl,
    int mode, char* smem)
{
    const uint32_t sb = sm_u32(smem);
    const int K = DIM, N = DIM;

    const int tid  = threadIdx.x;          // 0..127
    const int wid  = tid >> 5;             // 0..3
    const int lane = tid & 31;
    const int bm   = blockIdx.y;
    const int bn   = blockIdx.x;

    auto load_chunk = [&](int st, int c) {
        const uint32_t stb = sb + st * G2_STAGE + tid * G2_PITCH;
        const size_t xo = (size_t)(bm * 128 + tid) * K + c * 32;
        const size_t wo = (size_t)(bn * 128 + tid) * K + c * 32;
#pragma unroll
        for (int i = 0; i < 4; i++) {
            cp_async16(stb + 0 * G2_ARR + i * 16, Xh + xo + i * 8);
            cp_async16(stb + 1 * G2_ARR + i * 16, Xl + xo + i * 8);
            cp_async16(stb + 2 * G2_ARR + i * 16, W  + wo + i * 8);
        }
        CP_COMMIT();
    };

    load_chunk(0, 0);
    load_chunk(1, 1);

    const int wm = (wid & 1) * 64;
    const int wn = (wid >> 1) * 64;
    const int g  = lane >> 2;
    const int t  = lane & 3;
    const int a_row = (lane & 7) + ((lane >> 3) & 1) * 8;
    const int a_chi = lane >> 4;
    const int b_row = (lane & 7) + ((lane >> 4) & 1) * 8;
    const int b_chi = (lane >> 3) & 1;

    float acc[4][8][4];
#pragma unroll
    for (int mt = 0; mt < 4; mt++)
#pragma unroll
        for (int nt = 0; nt < 8; nt++)
#pragma unroll
            for (int e = 0; e < 4; e++) acc[mt][nt][e] = 0.f;

    for (int c = 0; c < 32; c++) {
        CP_WAIT1();
        __syncthreads();
        const uint32_t stb = sb + (c & 1) * G2_STAGE;

#pragma unroll
        for (int ks = 0; ks < 2; ks++) {
            uint32_t Ah[4][4], Al[4][4], Bw[4][4];
#pragma unroll
            for (int mt = 0; mt < 4; mt++) {
                const uint32_t ro = (uint32_t)((wm + mt * 16 + a_row) * G2_PITCH
                                  + ((ks * 2 + a_chi) << 4));
                ldsm_x4(Ah[mt], stb + 0 * G2_ARR + ro);
                ldsm_x4(Al[mt], stb + 1 * G2_ARR + ro);
            }
#pragma unroll
            for (int p = 0; p < 4; p++) {
                const uint32_t ro = (uint32_t)((wn + p * 16 + b_row) * G2_PITCH
                                  + ((ks * 2 + b_chi) << 4));
                ldsm_x4(Bw[p], stb + 2 * G2_ARR + ro);
            }
#pragma unroll
            for (int mt = 0; mt < 4; mt++)
#pragma unroll
                for (int nt = 0; nt < 8; nt++) {
                    const int p = nt >> 1, s2 = (nt & 1) * 2;
                    uint32_t bw[2] = {Bw[p][s2], Bw[p][s2 + 1]};
                    mma_f16(acc[mt][nt], Ah[mt], bw);
                    mma_f16(acc[mt][nt], Al[mt], bw);
                }
        }

        __syncthreads();
        if (c + 2 < 32) load_chunk(c & 1, c + 2);
        else            CP_COMMIT();
    }

#pragma unroll
    for (int mt = 0; mt < 4; mt++) {
        const int row = bm * 128 + wm + mt * 16 + g;
#pragma unroll
        for (int nt = 0; nt < 8; nt++) {
            const int col = bn * 128 + wn + nt * 8 + 2 * t;
            float2 bi = *(const float2*)&bias[col];
            const float c0 = acc[mt][nt][0] + bi.x;
            const float c1 = acc[mt][nt][1] + bi.y;
            const float c2 = acc[mt][nt][2] + bi.x;
            const float c3 = acc[mt][nt][3] + bi.y;
            if (mode == 1) {
                uint32_t h0, l0, h1, l1;
                packsplit2h(c0, c1, h0, l0);
                packsplit2h(c2, c3, h1, l1);
                *(uint32_t*)&Yh[(size_t)row * N + col]       = h0;
                *(uint32_t*)&Yl[(size_t)row * N + col]       = l0;
                *(uint32_t*)&Yh[(size_t)(row + 8) * N + col] = h1;
                *(uint32_t*)&Yl[(size_t)(row + 8) * N + col] = l1;
            } else {
                *(uint32_t*)&Yh[(size_t)row * N + col]       = packh2(c0, c1);
                *(uint32_t*)&Yh[(size_t)(row + 8) * N + col] = packh2(c2, c3);
            }
        }
    }
}

__global__ __launch_bounds__(128, 2)
void gemm_qkv_kernel(const float* __restrict__ bq, const float* __restrict__ bk,
                     const float* __restrict__ bv)
{
    extern __shared__ char smem[];
    const int z = blockIdx.z;
    if (z == 0)      gemm2_core(g_xqh, g_xql, g_w16q, bq, g_qh, g_ql, 1, smem);
    else if (z == 1) gemm2_core(g_xkh, g_xkl, g_w16k, bk, g_k16, nullptr, 2, smem);
    else             gemm2_core(g_xvh, g_xvl, g_w16v, bv, g_v16, nullptr, 2, smem);
}

// ===========================================================================
// bf16 3-pass GEMM (O-projection; error anchor)
// CTA 128x128, 128 THREADS (4 warps, 64x64 each, 256 regs), K-chunk 32.
// ===========================================================================
#define GK_PITCH 80
#define GK_ARR   (128 * GK_PITCH)
#define GK_STAGE (4 * GK_ARR)
#define GK_DSMEM (2 * GK_STAGE)        // 81920 -> 2 CTAs/SM

__global__ __launch_bounds__(128, 2)
void gemm_o_kernel(const float* __restrict__ bo, float* __restrict__ out)
{
    extern __shared__ char smem[];
    const uint32_t sb = sm_u32(smem);
    const int K = DIM, N = DIM;

    const int tid  = threadIdx.x;          // 0..127
    const int wid  = tid >> 5;
    const int lane = tid & 31;
    const int bm   = blockIdx.y;
    const int bn   = blockIdx.x;

    auto load_chunk = [&](int st, int c) {
        const uint32_t stb = sb + st * GK_STAGE + tid * GK_PITCH;
        const int k0 = c * 32;
        const __nv_bfloat16* s0 = g_xh  + (size_t)(bm * 128 + tid) * K + k0;
        const __nv_bfloat16* s1 = g_xl  + (size_t)(bm * 128 + tid) * K + k0;
        const __nv_bfloat16* s2 = g_woh + (size_t)(bn * 128 + tid) * K + k0;
        const __nv_bfloat16* s3 = g_wol + (size_t)(bn * 128 + tid) * K + k0;
#pragma unroll
        for (int i = 0; i < 4; i++) {
            const uint32_t off = (uint32_t)(i << 4);
            cp_async16(stb + 0 * GK_ARR + off, s0 + i * 8);
            cp_async16(stb + 1 * GK_ARR + off, s1 + i * 8);
            cp_async16(stb + 2 * GK_ARR + off, s2 + i * 8);
            cp_async16(stb + 3 * GK_ARR + off, s3 + i * 8);
        }
        CP_COMMIT();
    };

    load_chunk(0, 0);
    load_chunk(1, 1);

    const int wm = (wid & 1) * 64;
    const int wn = (wid >> 1) * 64;
    const int g  = lane >> 2;
    const int t  = lane & 3;
    const int a_row = (lane & 7) + ((lane >> 3) & 1) * 8;
    const int a_chi = lane >> 4;
    const int b_row = (lane & 7) + ((lane >> 4) & 1) * 8;
    const int b_chi = (lane >> 3) & 1;

    float acc[4][8][4];
#pragma unroll
    for (int mt = 0; mt < 4; mt++)
#pragma unroll
        for (int nt = 0; nt < 8; nt++)
#pragma unroll
            for (int e = 0; e < 4; e++) acc[mt][nt][e] = 0.f;

    for (int c = 0; c < 32; c++) {
        CP_WAIT1();
        __syncthreads();
        const uint32_t stb = sb + (c & 1) * GK_STAGE;

#pragma unroll
        for (int ks = 0; ks < 2; ks++) {
            uint32_t Ah[4][4], Al[4][4], Bh[4][4], Bl[4][4];
#pragma unroll
            for (int mt = 0; mt < 4; mt++) {
                const uint32_t ro = (uint32_t)((wm + mt * 16 + a_row) * GK_PITCH
                                  + ((ks * 2 + a_chi) << 4));
                ldsm_x4(Ah[mt], stb + 0 * GK_ARR + ro);
                ldsm_x4(Al[mt], stb + 1 * GK_ARR + ro);
            }
#pragma unroll
            for (int p = 0; p < 4; p++) {
                const uint32_t ro = (uint32_t)((wn + p * 16 + b_row) * GK_PITCH
                                  + ((ks * 2 + b_chi) << 4));
                ldsm_x4(Bh[p], stb + 2 * GK_ARR + ro);
                ldsm_x4(Bl[p], stb + 3 * GK_ARR + ro);
            }
#pragma unroll
            for (int mt = 0; mt < 4; mt++)
#pragma unroll
                for (int nt = 0; nt < 8; nt++) {
                    const int p = nt >> 1, s2 = (nt & 1) * 2;
                    uint32_t bh[2] = {Bh[p][s2], Bh[p][s2 + 1]};
                    uint32_t bl[2] = {Bl[p][s2], Bl[p][s2 + 1]};
                    mma_bf16(acc[mt][nt], Ah[mt], bh);
                    mma_bf16(acc[mt][nt], Al[mt], bh);
                    mma_bf16(acc[mt][nt], Ah[mt], bl);
                }
        }

        __syncthreads();
        if (c + 2 < 32) load_chunk(c & 1, c + 2);
        else            CP_COMMIT();
    }

#pragma unroll
    for (int mt = 0; mt < 4; mt++) {
        const int row = bm * 128 + wm + mt * 16 + g;
#pragma unroll
        for (int nt = 0; nt < 8; nt++) {
            const int col = bn * 128 + wn + nt * 8 + 2 * t;
            float2 bi = *(const float2*)&bo[col];
            float2 r01 = {acc[mt][nt][0] + bi.x, acc[mt][nt][1] + bi.y};
            float2 r23 = {acc[mt][nt][2] + bi.x, acc[mt][nt][3] + bi.y};
            *(float2*)&out[(size_t)row * N + col]       = r01;
            *(float2*)&out[(size_t)(row + 8) * N + col] = r23;
        }
    }
}

// ===========================================================================
// Flash attention (unchanged round-15 champion):
// QK^T fp16 2-pass (Q h/l, K single); softmax fp16 exp2; PV fp16 single-pass
// with V natural + ldmatrix.trans; row sums via ones-B MMA.
// ===========================================================================
#define AT_PITCHB 144
#define AT_QBYTES (128 * AT_PITCHB)        // 18432 per Q array
#define AT_KARR   (64 * AT_PITCHB)         // 9216
#define AT_ST0    (2 * AT_QBYTES)          // 36864
#define AT_STSZ   (2 * AT_KARR)            // 18432: K16, V16
#define AT_SMEM   (AT_ST0 + 2 * AT_STSZ)   // 73728 -> 2 CTAs/SM
#define L2E       1.4426950408889634f

__global__ __launch_bounds__(256, 2)
void attn_mma_kernel()
{
    extern __shared__ char smem[];
    const uint32_t sbase = sm_u32(smem);

    const int tid  = threadIdx.x;
    const int wid  = tid >> 5;
    const int lane = tid & 31;
    const int g    = lane >> 2;
    const int t    = lane & 3;
    const int b_row = (lane & 7) + ((lane >> 4) & 1) * 8;
    const int b_chi = (lane >> 3) & 1;
    const int v_row = lane & 15;
    const int v_dof = (lane >> 4) * 16;
    const int qt   = blockIdx.x;
    const int bh   = blockIdx.y;
    const int bb   = bh >> 4, hh = bh & 15;
    const int ho   = bb * 1024 + hh * 64;

    // ---- Q tile load (fp16 h/l) ----
    {
        const int r  = tid >> 1;
        const int c0 = (tid & 1) * 4;
        const __half* sh = g_qh + (size_t)(qt * 128 + r) * 2048 + ho + c0 * 8;
        const __half* sl = g_ql + (size_t)(qt * 128 + r) * 2048 + ho + c0 * 8;
        const uint32_t dh = sbase + r * AT_PITCHB + c0 * 16;
        const uint32_t dl = dh + AT_QBYTES;
#pragma unroll
        for (int i = 0; i < 4; i++) {
            cp_async16(dh + i * 16, sh + i * 8);
            cp_async16(dl + i * 16, sl + i * 8);
        }
        CP_COMMIT();
    }

    auto load_stage = [&](int s, int kt) {
        const uint32_t stb = sbase + AT_ST0 + s * AT_STSZ;
        const int which = tid >> 7;
        const int r  = (tid >> 1) & 63;
        const int hf = tid & 1;
        const __half* src = (which == 0 ? g_k16 : g_v16)
                          + (size_t)(kt * 64 + r) * 2048 + ho + hf * 32;
        const uint32_t dst = stb + which * AT_KARR + r * AT_PITCHB + hf * 64;
#pragma unroll
        for (int i = 0; i < 4; i++) cp_async16(dst + i * 16, src + i * 8);
        CP_COMMIT();
    };

    load_stage(0, 0);
    load_stage(1, 1);

    CP_WAIT2();
    __syncthreads();
    uint32_t qah[4][4], qal[4][4];
    {
        const char* Qh0 = smem + (wid * 16 + g) * AT_PITCHB + 4 * t;
        const char* Ql0 = Qh0 + AT_QBYTES;
#pragma unroll
        for (int ks = 0; ks < 4; ks++) {
            const int ko = ks * 32;
            qah[ks][0] = *(const uint32_t*)(Qh0 + ko);
            qah[ks][1] = *(const uint32_t*)(Qh0 + 8 * AT_PITCHB + ko);
            qah[ks][2] = *(const uint32_t*)(Qh0 + ko + 16);
            qah[ks][3] = *(const uint32_t*)(Qh0 + 8 * AT_PITCHB + ko + 16);
            qal[ks][0] = *(const uint32_t*)(Ql0 + ko);
            qal[ks][1] = *(const uint32_t*)(Ql0 + 8 * AT_PITCHB + ko);
            qal[ks][2] = *(const uint32_t*)(Ql0 + ko + 16);
            qal[ks][3] = *(const uint32_t*)(Ql0 + 8 * AT_PITCHB + ko + 16);
        }
    }

    const uint32_t ONES2 = 0x3C003C00u;
    const uint32_t onesb[2] = {ONES2, ONES2};

    float m0 = -1e30f, m1 = -1e30f;
    float ls[4] = {0.f, 0.f, 0.f, 0.f};
    float o[8][4];
#pragma unroll
    for (int nt = 0; nt < 8; nt++)
#pragma unroll
        for (int e = 0; e < 4; e++) o[nt][e] = 0.f;

    for (int kt = 0; kt < SEQ / 64; kt++) {
        CP_WAIT1();
        __syncthreads();
        const uint32_t stpu = sbase + AT_ST0 + (kt & 1) * AT_STSZ;

        float sc[8][4];
#pragma unroll
        for (int nt = 0; nt < 8; nt++)
#pragma unroll
            for (int e = 0; e < 4; e++) sc[nt][e] = 0.f;

#pragma unroll
        for (int ks = 0; ks < 4; ks++) {
#pragma unroll
            for (int p = 0; p < 4; p++) {
                const uint32_t ro = (uint32_t)((p * 16 + b_row) * AT_PITCHB
                                  + ((ks * 2 + b_chi) << 4));
                uint32_t Bk[4];
                ldsm_x4(Bk, stpu + ro);
#pragma unroll
                for (int ntl = 0; ntl < 2; ntl++) {
                    const int nt = p * 2 + ntl;
                    uint32_t bkf[2] = {Bk[ntl * 2], Bk[ntl * 2 + 1]};
                    mma_f16(sc[nt], qah[ks], bkf);
                    mma_f16(sc[nt], qal[ks], bkf);
                }
            }
        }

        float mx0 = -1e30f, mx1 = -1e30f;
#pragma unroll
        for (int nt = 0; nt < 8; nt++) {
            mx0 = fmaxf(mx0, fmaxf(sc[nt][0], sc[nt][1]));
            mx1 = fmaxf(mx1, fmaxf(sc[nt][2], sc[nt][3]));
        }
        mx0 = fmaxf(mx0, __shfl_xor_sync(0xffffffffu, mx0, 1));
        mx0 = fmaxf(mx0, __shfl_xor_sync(0xffffffffu, mx0, 2));
        mx1 = fmaxf(mx1, __shfl_xor_sync(0xffffffffu, mx1, 1));
        mx1 = fmaxf(mx1, __shfl_xor_sync(0xffffffffu, mx1, 2));
        const float mn0 = fmaxf(m0, mx0), mn1 = fmaxf(m1, mx1);
        const float a0 = __expf(m0 - mn0), a1 = __expf(m1 - mn1);
        m0 = mn0;  m1 = mn1;
        const float mb0 = mn0 * L2E, mb1 = mn1 * L2E;

#pragma unroll
        for (int nt = 0; nt < 8; nt++) {
            o[nt][0] *= a0; o[nt][1] *= a0;
            o[nt][2] *= a1; o[nt][3] *= a1;
        }
        ls[0] *= a0; ls[1] *= a0; ls[2] *= a1; ls[3] *= a1;

#pragma unroll
        for (int js = 0; js < 4; js++) {
            const int n0 = 2 * js, n1 = 2 * js + 1;
            uint32_t pa[4];
            pa[0] = exp2_f16x2(packh2(fmaf(sc[n0][0], L2E, -mb0),
                                      fmaf(sc[n0][1], L2E, -mb0)));
            pa[1] = exp2_f16x2(packh2(fmaf(sc[n0][2], L2E, -mb1),
                                      fmaf(sc[n0][3], L2E, -mb1)));
            pa[2] = exp2_f16x2(packh2(fmaf(sc[n1][0], L2E, -mb0),
                                      fmaf(sc[n1][1], L2E, -mb0)));
            pa[3] = exp2_f16x2(packh2(fmaf(sc[n1][2], L2E, -mb1),
                                      fmaf(sc[n1][3], L2E, -mb1)));
            mma_f16(ls, pa, onesb);
#pragma unroll
            for (int p = 0; p < 4; p++) {
                const uint32_t ro = (uint32_t)((js * 16 + v_row) * AT_PITCHB
                                  + p * 32 + v_dof);
                uint32_t Bv[4];
                ldsm_x4_trans(Bv, stpu + AT_KARR + ro);
                uint32_t bv0[2] = {Bv[0], Bv[1]};
                uint32_t bv1[2] = {Bv[2], Bv[3]};
                mma_f16(o[p * 2],     pa, bv0);
                mma_f16(o[p * 2 + 1], pa, bv1);
            }
        }

        __syncthreads();
        if (kt + 2 < SEQ / 64) load_stage(kt & 1, kt + 2);
        else                   CP_COMMIT();
    }

    const float li0 = 1.f / ls[0], li1 = 1.f / ls[2];
    const int row0 = qt * 128 + wid * 16 + g;
#pragma unroll
    for (int nt = 0; nt < 8; nt++) {
        const int col = ho + nt * 8 + 2 * t;
        uint32_t h0, lo0, h1, lo1;
        packsplit2(o[nt][0] * li0, o[nt][1] * li0, h0, lo0);
        packsplit2(o[nt][2] * li1, o[nt][3] * li1, h1, lo1);
        *(uint32_t*)&g_xh[(size_t)row0 * 2048 + col]       = h0;
        *(uint32_t*)&g_xl[(size_t)row0 * 2048 + col]       = lo0;
        *(uint32_t*)&g_xh[(size_t)(row0 + 8) * 2048 + col] = h1;
        *(uint32_t*)&g_xl[(size_t)(row0 + 8) * 2048 + col] = lo1;
    }
}

// ---------------------------------------------------------------------------
// kernel_launch
// ---------------------------------------------------------------------------
extern "C" void kernel_launch(void* const* d_in, const int* in_sizes, int n_in,
                              void* d_out, int out_size)
{
    const float* query = (const float*)d_in[0];
    const float* key   = (const float*)d_in[1];
    const float* value = (const float*)d_in[2];
    const float* Wq    = (const float*)d_in[3];
    const float* bq    = (const float*)d_in[4];
    const float* Wk    = (const float*)d_in[5];
    const float* bk    = (const float*)d_in[6];
    const float* Wv    = (const float*)d_in[7];
    const float* bv    = (const float*)d_in[8];
    const float* Wo    = (const float*)d_in[9];
    const float* bo    = (const float*)d_in[10];
    float* out = (float*)d_out;

    cudaFuncSetAttribute(gemm_qkv_kernel,
                         cudaFuncAttributeMaxDynamicSharedMemorySize, G2_DSMEM);
    cudaFuncSetAttribute(gemm_o_kernel,
                         cudaFuncAttributeMaxDynamicSharedMemorySize, GK_DSMEM);
    cudaFuncSetAttribute(attn_mma_kernel,
                         cudaFuncAttributeMaxDynamicSharedMemorySize, AT_SMEM);

    split_all_kernel<<<dim3(NTOT / 1024, 7), 256>>>(query, key, value, Wq, Wk, Wv, Wo);

    gemm_qkv_kernel<<<dim3(DIM / 128, MTOK / 128, 3), 128, G2_DSMEM>>>(bq, bk, bv);

    attn_mma_kernel<<<dim3(SEQ / 128, BATCH * NH), 256, AT_SMEM>>>();

    gemm_o_kernel<<<dim3(DIM / 128, MTOK / 128), 128, GK_DSMEM>>>(bo, out);
}

// round 17
// speedup vs baseline: 1.1653x; 1.1653x over previous
#include <cuda_runtime.h>
#include <cuda_bf16.h>
#include <cuda_fp16.h>
#include <cstdint>

// Problem constants
#define SEQ   2048
#define BATCH 2
#define DIM   1024
#define NH    16
#define HD    64
#define MTOK  (SEQ * BATCH)   // 4096 tokens
#define NTOT  (MTOK * DIM)    // 4M elements
#define NW    (DIM * DIM)     // 1M weight elements

// Scratch (allocation-free rule: __device__ globals)
// input splits (fp16 2-term)
__device__ __half g_xqh[NTOT], g_xql[NTOT];
__device__ __half g_xkh[NTOT], g_xkl[NTOT];
__device__ __half g_xvh[NTOT], g_xvl[NTOT];
// weights: QKV single fp16; O bf16 2-term
__device__ __half g_w16q[NW], g_w16k[NW], g_w16v[NW];
__device__ __nv_bfloat16 g_woh[NW], g_wol[NW];
// projected Q (fp16 2-term), K (fp16 single), V (fp16 single, natural layout)
__device__ __half g_qh[NTOT], g_ql[NTOT];
__device__ __half g_k16[NTOT];
__device__ __half g_v16[NTOT];
// attention output (bf16 2-term, feeds O-proj 3-pass)
__device__ __nv_bfloat16 g_xh[NTOT], g_xl[NTOT];

// ===========================================================================
// Helpers (family-safe PTX: cp.async, mma.sync, ldmatrix(+trans), ex2.f16x2)
// ===========================================================================
__device__ __forceinline__ uint32_t sm_u32(const void* p) {
    return (uint32_t)__cvta_generic_to_shared(p);
}
__device__ __forceinline__ void cp_async16(uint32_t smem_addr, const void* gptr) {
    asm volatile("cp.async.cg.shared.global [%0], [%1], 16;" :: "r"(smem_addr), "l"(gptr) : "memory");
}
#define CP_COMMIT() asm volatile("cp.async.commit_group;" ::: "memory")
#define CP_WAIT1()  asm volatile("cp.async.wait_group 1;" ::: "memory")
#define CP_WAIT2()  asm volatile("cp.async.wait_group 2;" ::: "memory")

__device__ __forceinline__ void mma_bf16(float* c, const uint32_t* a, const uint32_t* b) {
    asm volatile(
        "mma.sync.aligned.m16n8k16.row.col.f32.bf16.bf16.f32 "
        "{%0,%1,%2,%3}, {%4,%5,%6,%7}, {%8,%9}, {%0,%1,%2,%3};"
        : "+f"(c[0]), "+f"(c[1]), "+f"(c[2]), "+f"(c[3])
        : "r"(a[0]), "r"(a[1]), "r"(a[2]), "r"(a[3]), "r"(b[0]), "r"(b[1]));
}
__device__ __forceinline__ void mma_f16(float* c, const uint32_t* a, const uint32_t* b) {
    asm volatile(
        "mma.sync.aligned.m16n8k16.row.col.f32.f16.f16.f32 "
        "{%0,%1,%2,%3}, {%4,%5,%6,%7}, {%8,%9}, {%0,%1,%2,%3};"
        : "+f"(c[0]), "+f"(c[1]), "+f"(c[2]), "+f"(c[3])
        : "r"(a[0]), "r"(a[1]), "r"(a[2]), "r"(a[3]), "r"(b[0]), "r"(b[1]));
}
__device__ __forceinline__ void ldsm_x4(uint32_t* r, uint32_t addr) {
    asm volatile("ldmatrix.sync.aligned.m8n8.x4.shared.b16 {%0,%1,%2,%3}, [%4];"
                 : "=r"(r[0]), "=r"(r[1]), "=r"(r[2]), "=r"(r[3]) : "r"(addr));
}
__device__ __forceinline__ void ldsm_x4_trans(uint32_t* r, uint32_t addr) {
    asm volatile("ldmatrix.sync.aligned.m8n8.x4.trans.shared.b16 {%0,%1,%2,%3}, [%4];"
                 : "=r"(r[0]), "=r"(r[1]), "=r"(r[2]), "=r"(r[3]) : "r"(addr));
}
__device__ __forceinline__ uint32_t exp2_f16x2(uint32_t x) {
    uint32_t r;
    asm("ex2.approx.f16x2 %0, %1;" : "=r"(r) : "r"(x));
    return r;
}

// bf16 2-term split pack
__device__ __forceinline__ void packsplit2(float x, float y, uint32_t& h, uint32_t& l) {
    __nv_bfloat162 hb = __float22bfloat162_rn(make_float2(x, y));
    h = *reinterpret_cast<uint32_t*>(&hb);
    float rx = x - __low2float(hb);
    float ry = y - __high2float(hb);
    __nv_bfloat162 lb = __float22bfloat162_rn(make_float2(rx, ry));
    l = *reinterpret_cast<uint32_t*>(&lb);
}
// fp16 2-term split pack
__device__ __forceinline__ void packsplit2h(float x, float y, uint32_t& h, uint32_t& l) {
    __half2 hb = __float22half2_rn(make_float2(x, y));
    h = *reinterpret_cast<uint32_t*>(&hb);
    float rx = x - __low2float(hb);
    float ry = y - __high2float(hb);
    __half2 lb = __float22half2_rn(make_float2(rx, ry));
    l = *reinterpret_cast<uint32_t*>(&lb);
}
__device__ __forceinline__ uint32_t packh2(float x, float y) {
    __half2 hp = __float22half2_rn(make_float2(x, y));
    return *reinterpret_cast<uint32_t*>(&hp);
}

// ===========================================================================
// Prep: merged split kernel, MLP=4 (4 independent float4 loads per thread)
//   y 0..2 : inputs q,k,v -> fp16 h/l
//   y 3..5 : Wq,Wk,Wv     -> single fp16
//   y 6    : Wo           -> bf16 h/l
// Each thread handles 16 consecutive floats.
// ===========================================================================
__global__ __launch_bounds__(256)
void split_all_kernel(const float* __restrict__ q, const float* __restrict__ k,
                      const float* __restrict__ v,
                      const float* __restrict__ wq, const float* __restrict__ wk,
                      const float* __restrict__ wv, const float* __restrict__ wo)
{
    const int y = blockIdx.y;
    const int base = (blockIdx.x * 256 + threadIdx.x) * 16;
    if (y < 3) {
        const float* src = (y == 0) ? q : (y == 1) ? k : v;
        __half* hd = (y == 0) ? g_xqh : (y == 1) ? g_xkh : g_xvh;
        __half* ld = (y == 0) ? g_xql : (y == 1) ? g_xkl : g_xvl;
        float4 t[4];
#pragma unroll
        for (int j = 0; j < 4; j++) t[j] = *(const float4*)(src + base + j * 4);
        uint32_t h[8], l[8];
#pragma unroll
        for (int j = 0; j < 4; j++) {
            packsplit2h(t[j].x, t[j].y, h[2 * j],     l[2 * j]);
            packsplit2h(t[j].z, t[j].w, h[2 * j + 1], l[2 * j + 1]);
        }
        uint4 h0 = {h[0], h[1], h[2], h[3]}, h1 = {h[4], h[5], h[6], h[7]};
        uint4 l0 = {l[0], l[1], l[2], l[3]}, l1 = {l[4], l[5], l[6], l[7]};
        *(uint4*)(hd + base)     = h0;
        *(uint4*)(hd + base + 8) = h1;
        *(uint4*)(ld + base)     = l0;
        *(uint4*)(ld + base + 8) = l1;
    } else if (y < 6) {
        if (base >= NW) return;
        const int w = y - 3;
        const float* src = (w == 0) ? wq : (w == 1) ? wk : wv;
        __half* hd = (w == 0) ? g_w16q : (w == 1) ? g_w16k : g_w16v;
        float4 t[4];
#pragma unroll
        for (int j = 0; j < 4; j++) t[j] = *(const float4*)(src + base + j * 4);
        uint4 h0, h1;
        h0.x = packh2(t[0].x, t[0].y); h0.y = packh2(t[0].z, t[0].w);
        h0.z = packh2(t[1].x, t[1].y); h0.w = packh2(t[1].z, t[1].w);
        h1.x = packh2(t[2].x, t[2].y); h1.y = packh2(t[2].z, t[2].w);
        h1.z = packh2(t[3].x, t[3].y); h1.w = packh2(t[3].z, t[3].w);
        *(uint4*)(hd + base)     = h0;
        *(uint4*)(hd + base + 8) = h1;
    } else {
        if (base >= NW) return;
        float4 t[4];
#pragma unroll
        for (int j = 0; j < 4; j++) t[j] = *(const float4*)(wo + base + j * 4);
        uint32_t h[8], l[8];
#pragma unroll
        for (int j = 0; j < 4; j++) {
            packsplit2(t[j].x, t[j].y, h[2 * j],     l[2 * j]);
            packsplit2(t[j].z, t[j].w, h[2 * j + 1], l[2 * j + 1]);
        }
        uint4 h0 = {h[0], h[1], h[2], h[3]}, h1 = {h[4], h[5], h[6], h[7]};
        uint4 l0 = {l[0], l[1], l[2], l[3]}, l1 = {l[4], l[5], l[6], l[7]};
        *(uint4*)(g_woh + base)     = h0;
        *(uint4*)(g_woh + base + 8) = h1;
        *(uint4*)(g_wol + base)     = l0;
        *(uint4*)(g_wol + base + 8) = l1;
    }
}

// ===========================================================================
// fp16 2-pass GEMM: Y = (Xh+Xl)@W16^T + bias   (round-15 config)
// CTA 128x128, 8 warps (64x32), K-chunk 32, 2-stage, pitch-80 rows.
// Epilogue modes: 1 = fp16 h/l out, 2 = fp16 single out.
// ===========================================================================
#define G2_PITCH 80
#define G2_ARR   (128 * G2_PITCH)       // 10240
#define G2_STAGE (3 * G2_ARR)           // 30720: Xh, Xl, W
#define G2_DSMEM (2 * G2_STAGE)         // 61440 -> 2 CTAs/SM

__device__ __forceinline__ void gemm2_core(
    const __half* __restrict__ Xh, const __half* __restrict__ Xl,
    const __half* __restrict__ W, const float* __restrict__ bias,
    __half* __restrict__ Yh, __half* __restrict__ Yl,
    int mode, char* smem)
{
    const uint32_t sb = sm_u32(smem);
    const int K = DIM, N = DIM;

    const int tid  = threadIdx.x;
    const int wid  = tid >> 5;
    const int lane = tid & 31;
    const int bm   = blockIdx.y;
    const int bn   = blockIdx.x;

    const int lrow = tid >> 1;
    const int half = tid & 1;

    auto load_chunk = [&](int st, int c) {
        const uint32_t stb = sb + st * G2_STAGE + lrow * G2_PITCH + half * 32;
        const size_t xo = (size_t)(bm * 128 + lrow) * K + c * 32 + half * 16;
        const size_t wo = (size_t)(bn * 128 + lrow) * K + c * 32 + half * 16;
#pragma unroll
        for (int i = 0; i < 2; i++) {
            cp_async16(stb + 0 * G2_ARR + i * 16, Xh + xo + i * 8);
            cp_async16(stb + 1 * G2_ARR + i * 16, Xl + xo + i * 8);
            cp_async16(stb + 2 * G2_ARR + i * 16, W  + wo + i * 8);
        }
        CP_COMMIT();
    };

    load_chunk(0, 0);
    load_chunk(1, 1);

    const int wm = (wid & 1) * 64;
    const int wn = (wid >> 1) * 32;
    const int g  = lane >> 2;
    const int t  = lane & 3;
    const int a_row = (lane & 7) + ((lane >> 3) & 1) * 8;
    const int a_chi = lane >> 4;
    const int b_row = (lane & 7) + ((lane >> 4) & 1) * 8;
    const int b_chi = (lane >> 3) & 1;

    float acc[4][4][4];
#pragma unroll
    for (int mt = 0; mt < 4; mt++)
#pragma unroll
        for (int nt = 0; nt < 4; nt++)
#pragma unroll
            for (int e = 0; e < 4; e++) acc[mt][nt][e] = 0.f;

    for (int c = 0; c < 32; c++) {
        CP_WAIT1();
        __syncthreads();
        const uint32_t stb = sb + (c & 1) * G2_STAGE;

#pragma unroll
        for (int ks = 0; ks < 2; ks++) {
            uint32_t Ah[4][4], Al[4][4], Bw[2][4];
#pragma unroll
            for (int mt = 0; mt < 4; mt++) {
                const uint32_t ro = (uint32_t)((wm + mt * 16 + a_row) * G2_PITCH
                                  + ((ks * 2 + a_chi) << 4));
                ldsm_x4(Ah[mt], stb + 0 * G2_ARR + ro);
                ldsm_x4(Al[mt], stb + 1 * G2_ARR + ro);
            }
#pragma unroll
            for (int p = 0; p < 2; p++) {
                const uint32_t ro = (uint32_t)((wn + p * 16 + b_row) * G2_PITCH
                                  + ((ks * 2 + b_chi) << 4));
                ldsm_x4(Bw[p], stb + 2 * G2_ARR + ro);
            }
#pragma unroll
            for (int mt = 0; mt < 4; mt++)
#pragma unroll
                for (int nt = 0; nt < 4; nt++) {
                    const int p = nt >> 1, s2 = (nt & 1) * 2;
                    uint32_t bw[2] = {Bw[p][s2], Bw[p][s2 + 1]};
                    mma_f16(acc[mt][nt], Ah[mt], bw);
                    mma_f16(acc[mt][nt], Al[mt], bw);
                }
        }

        __syncthreads();
        if (c + 2 < 32) load_chunk(c & 1, c + 2);
        else            CP_COMMIT();
    }

#pragma unroll
    for (int mt = 0; mt < 4; mt++) {
        const int row = bm * 128 + wm + mt * 16 + g;
#pragma unroll
        for (int nt = 0; nt < 4; nt++) {
            const int col = bn * 128 + wn + nt * 8 + 2 * t;
            float2 bi = *(const float2*)&bias[col];
            const float c0 = acc[mt][nt][0] + bi.x;
            const float c1 = acc[mt][nt][1] + bi.y;
            const float c2 = acc[mt][nt][2] + bi.x;
            const float c3 = acc[mt][nt][3] + bi.y;
            if (mode == 1) {
                uint32_t h0, l0, h1, l1;
                packsplit2h(c0, c1, h0, l0);
                packsplit2h(c2, c3, h1, l1);
                *(uint32_t*)&Yh[(size_t)row * N + col]       = h0;
                *(uint32_t*)&Yl[(size_t)row * N + col]       = l0;
                *(uint32_t*)&Yh[(size_t)(row + 8) * N + col] = h1;
                *(uint32_t*)&Yl[(size_t)(row + 8) * N + col] = l1;
            } else {
                *(uint32_t*)&Yh[(size_t)row * N + col]       = packh2(c0, c1);
                *(uint32_t*)&Yh[(size_t)(row + 8) * N + col] = packh2(c2, c3);
            }
        }
    }
}

__global__ __launch_bounds__(256, 2)
void gemm_qkv_kernel(const float* __restrict__ bq, const float* __restrict__ bk,
                     const float* __restrict__ bv)
{
    extern __shared__ char smem[];
    const int z = blockIdx.z;
    if (z == 0)      gemm2_core(g_xqh, g_xql, g_w16q, bq, g_qh, g_ql, 1, smem);
    else if (z == 1) gemm2_core(g_xkh, g_xkl, g_w16k, bk, g_k16, nullptr, 2, smem);
    else             gemm2_core(g_xvh, g_xvl, g_w16v, bv, g_v16, nullptr, 2, smem);
}

// ===========================================================================
// bf16 3-pass GEMM (O-projection; error anchor) — round-15 config.
// ===========================================================================
#define GK_PITCH 80
#define GK_ARR   (128 * GK_PITCH)
#define GK_STAGE (4 * GK_ARR)
#define GK_DSMEM (2 * GK_STAGE)        // 81920 -> 2 CTAs/SM

__global__ __launch_bounds__(256, 2)
void gemm_o_kernel(const float* __restrict__ bo, float* __restrict__ out)
{
    extern __shared__ char smem[];
    const uint32_t sb = sm_u32(smem);
    const int K = DIM, N = DIM;

    const int tid  = threadIdx.x;
    const int wid  = tid >> 5;
    const int lane = tid & 31;
    const int bm   = blockIdx.y;
    const int bn   = blockIdx.x;

    const int lrow = tid >> 1;
    const int lc0  = (tid & 1) * 2;

    auto load_chunk = [&](int st, int c) {
        const uint32_t stb = sb + st * GK_STAGE + lrow * GK_PITCH;
        const int k0 = c * 32;
        const __nv_bfloat16* s0 = g_xh  + (size_t)(bm * 128 + lrow) * K + k0;
        const __nv_bfloat16* s1 = g_xl  + (size_t)(bm * 128 + lrow) * K + k0;
        const __nv_bfloat16* s2 = g_woh + (size_t)(bn * 128 + lrow) * K + k0;
        const __nv_bfloat16* s3 = g_wol + (size_t)(bn * 128 + lrow) * K + k0;
#pragma unroll
        for (int i = 0; i < 2; i++) {
            const int ch = lc0 + i;
            const uint32_t off = (uint32_t)(ch << 4);
            cp_async16(stb + 0 * GK_ARR + off, s0 + ch * 8);
            cp_async16(stb + 1 * GK_ARR + off, s1 + ch * 8);
            cp_async16(stb + 2 * GK_ARR + off, s2 + ch * 8);
            cp_async16(stb + 3 * GK_ARR + off, s3 + ch * 8);
        }
        CP_COMMIT();
    };

    load_chunk(0, 0);
    load_chunk(1, 1);

    const int wm = (wid & 1) * 64;
    const int wn = (wid >> 1) * 32;
    const int g  = lane >> 2;
    const int t  = lane & 3;
    const int a_row = (lane & 7) + ((lane >> 3) & 1) * 8;
    const int a_chi = lane >> 4;
    const int b_row = (lane & 7) + ((lane >> 4) & 1) * 8;
    const int b_chi = (lane >> 3) & 1;

    float acc[4][4][4];
#pragma unroll
    for (int mt = 0; mt < 4; mt++)
#pragma unroll
        for (int nt = 0; nt < 4; nt++)
#pragma unroll
            for (int e = 0; e < 4; e++) acc[mt][nt][e] = 0.f;

    for (int c = 0; c < 32; c++) {
        CP_WAIT1();
        __syncthreads();
        const uint32_t stb = sb + (c & 1) * GK_STAGE;

#pragma unroll
        for (int ks = 0; ks < 2; ks++) {
            uint32_t Ah[4][4], Al[4][4], Bh[2][4], Bl[2][4];
#pragma unroll
            for (int mt = 0; mt < 4; mt++) {
                const uint32_t ro = (uint32_t)((wm + mt * 16 + a_row) * GK_PITCH
                                  + ((ks * 2 + a_chi) << 4));
                ldsm_x4(Ah[mt], stb + 0 * GK_ARR + ro);
                ldsm_x4(Al[mt], stb + 1 * GK_ARR + ro);
            }
#pragma unroll
            for (int p = 0; p < 2; p++) {
                const uint32_t ro = (uint32_t)((wn + p * 16 + b_row) * GK_PITCH
                                  + ((ks * 2 + b_chi) << 4));
                ldsm_x4(Bh[p], stb + 2 * GK_ARR + ro);
                ldsm_x4(Bl[p], stb + 3 * GK_ARR + ro);
            }
#pragma unroll
            for (int mt = 0; mt < 4; mt++)
#pragma unroll
                for (int nt = 0; nt < 4; nt++) {
                    const int p = nt >> 1, s2 = (nt & 1) * 2;
                    uint32_t bh[2] = {Bh[p][s2], Bh[p][s2 + 1]};
                    uint32_t bl[2] = {Bl[p][s2], Bl[p][s2 + 1]};
                    mma_bf16(acc[mt][nt], Ah[mt], bh);
                    mma_bf16(acc[mt][nt], Al[mt], bh);
                    mma_bf16(acc[mt][nt], Ah[mt], bl);
                }
        }

        __syncthreads();
        if (c + 2 < 32) load_chunk(c & 1, c + 2);
        else            CP_COMMIT();
    }

#pragma unroll
    for (int mt = 0; mt < 4; mt++) {
        const int row = bm * 128 + wm + mt * 16 + g;
#pragma unroll
        for (int nt = 0; nt < 4; nt++) {
            const int col = bn * 128 + wn + nt * 8 + 2 * t;
            float2 bi = *(const float2*)&bo[col];
            float2 r01 = {acc[mt][nt][0] + bi.x, acc[mt][nt][1] + bi.y};
            float2 r23 = {acc[mt][nt][2] + bi.x, acc[mt][nt][3] + bi.y};
            *(float2*)&out[(size_t)row * N + col]       = r01;
            *(float2*)&out[(size_t)(row + 8) * N + col] = r23;
        }
    }
}

// ===========================================================================
// Flash attention (unchanged round-15 champion):
// QK^T fp16 2-pass (Q h/l, K single); softmax fp16 exp2; PV fp16 single-pass
// with V natural + ldmatrix.trans; row sums via ones-B MMA.
// ===========================================================================
#define AT_PITCHB 144
#define AT_QBYTES (128 * AT_PITCHB)        // 18432 per Q array
#define AT_KARR   (64 * AT_PITCHB)         // 9216
#define AT_ST0    (2 * AT_QBYTES)          // 36864
#define AT_STSZ   (2 * AT_KARR)            // 18432: K16, V16
#define AT_SMEM   (AT_ST0 + 2 * AT_STSZ)   // 73728 -> 2 CTAs/SM
#define L2E       1.4426950408889634f

__global__ __launch_bounds__(256, 2)
void attn_mma_kernel()
{
    extern __shared__ char smem[];
    const uint32_t sbase = sm_u32(smem);

    const int tid  = threadIdx.x;
    const int wid  = tid >> 5;
    const int lane = tid & 31;
    const int g    = lane >> 2;
    const int t    = lane & 3;
    const int b_row = (lane & 7) + ((lane >> 4) & 1) * 8;
    const int b_chi = (lane >> 3) & 1;
    const int v_row = lane & 15;
    const int v_dof = (lane >> 4) * 16;
    const int qt   = blockIdx.x;
    const int bh   = blockIdx.y;
    const int bb   = bh >> 4, hh = bh & 15;
    const int ho   = bb * 1024 + hh * 64;

    // ---- Q tile load (fp16 h/l) ----
    {
        const int r  = tid >> 1;
        const int c0 = (tid & 1) * 4;
        const __half* sh = g_qh + (size_t)(qt * 128 + r) * 2048 + ho + c0 * 8;
        const __half* sl = g_ql + (size_t)(qt * 128 + r) * 2048 + ho + c0 * 8;
        const uint32_t dh = sbase + r * AT_PITCHB + c0 * 16;
        const uint32_t dl = dh + AT_QBYTES;
#pragma unroll
        for (int i = 0; i < 4; i++) {
            cp_async16(dh + i * 16, sh + i * 8);
            cp_async16(dl + i * 16, sl + i * 8);
        }
        CP_COMMIT();
    }

    auto load_stage = [&](int s, int kt) {
        const uint32_t stb = sbase + AT_ST0 + s * AT_STSZ;
        const int which = tid >> 7;
        const int r  = (tid >> 1) & 63;
        const int hf = tid & 1;
        const __half* src = (which == 0 ? g_k16 : g_v16)
                          + (size_t)(kt * 64 + r) * 2048 + ho + hf * 32;
        const uint32_t dst = stb + which * AT_KARR + r * AT_PITCHB + hf * 64;
#pragma unroll
        for (int i = 0; i < 4; i++) cp_async16(dst + i * 16, src + i * 8);
        CP_COMMIT();
    };

    load_stage(0, 0);
    load_stage(1, 1);

    CP_WAIT2();
    __syncthreads();
    uint32_t qah[4][4], qal[4][4];
    {
        const char* Qh0 = smem + (wid * 16 + g) * AT_PITCHB + 4 * t;
        const char* Ql0 = Qh0 + AT_QBYTES;
#pragma unroll
        for (int ks = 0; ks < 4; ks++) {
            const int ko = ks * 32;
            qah[ks][0] = *(const uint32_t*)(Qh0 + ko);
            qah[ks][1] = *(const uint32_t*)(Qh0 + 8 * AT_PITCHB + ko);
            qah[ks][2] = *(const uint32_t*)(Qh0 + ko + 16);
            qah[ks][3] = *(const uint32_t*)(Qh0 + 8 * AT_PITCHB + ko + 16);
            qal[ks][0] = *(const uint32_t*)(Ql0 + ko);
            qal[ks][1] = *(const uint32_t*)(Ql0 + 8 * AT_PITCHB + ko);
            qal[ks][2] = *(const uint32_t*)(Ql0 + ko + 16);
            qal[ks][3] = *(const uint32_t*)(Ql0 + 8 * AT_PITCHB + ko + 16);
        }
    }

    const uint32_t ONES2 = 0x3C003C00u;
    const uint32_t onesb[2] = {ONES2, ONES2};

    float m0 = -1e30f, m1 = -1e30f;
    float ls[4] = {0.f, 0.f, 0.f, 0.f};
    float o[8][4];
#pragma unroll
    for (int nt = 0; nt < 8; nt++)
#pragma unroll
        for (int e = 0; e < 4; e++) o[nt][e] = 0.f;

    for (int kt = 0; kt < SEQ / 64; kt++) {
        CP_WAIT1();
        __syncthreads();
        const uint32_t stpu = sbase + AT_ST0 + (kt & 1) * AT_STSZ;

        float sc[8][4];
#pragma unroll
        for (int nt = 0; nt < 8; nt++)
#pragma unroll
            for (int e = 0; e < 4; e++) sc[nt][e] = 0.f;

#pragma unroll
        for (int ks = 0; ks < 4; ks++) {
#pragma unroll
            for (int p = 0; p < 4; p++) {
                const uint32_t ro = (uint32_t)((p * 16 + b_row) * AT_PITCHB
                                  + ((ks * 2 + b_chi) << 4));
                uint32_t Bk[4];
                ldsm_x4(Bk, stpu + ro);
#pragma unroll
                for (int ntl = 0; ntl < 2; ntl++) {
                    const int nt = p * 2 + ntl;
                    uint32_t bkf[2] = {Bk[ntl * 2], Bk[ntl * 2 + 1]};
                    mma_f16(sc[nt], qah[ks], bkf);
                    mma_f16(sc[nt], qal[ks], bkf);
                }
            }
        }

        float mx0 = -1e30f, mx1 = -1e30f;
#pragma unroll
        for (int nt = 0; nt < 8; nt++) {
            mx0 = fmaxf(mx0, fmaxf(sc[nt][0], sc[nt][1]));
            mx1 = fmaxf(mx1, fmaxf(sc[nt][2], sc[nt][3]));
        }
        mx0 = fmaxf(mx0, __shfl_xor_sync(0xffffffffu, mx0, 1));
        mx0 = fmaxf(mx0, __shfl_xor_sync(0xffffffffu, mx0, 2));
        mx1 = fmaxf(mx1, __shfl_xor_sync(0xffffffffu, mx1, 1));
        mx1 = fmaxf(mx1, __shfl_xor_sync(0xffffffffu, mx1, 2));
        const float mn0 = fmaxf(m0, mx0), mn1 = fmaxf(m1, mx1);
        const float a0 = __expf(m0 - mn0), a1 = __expf(m1 - mn1);
        m0 = mn0;  m1 = mn1;
        const float mb0 = mn0 * L2E, mb1 = mn1 * L2E;

#pragma unroll
        for (int nt = 0; nt < 8; nt++) {
            o[nt][0] *= a0; o[nt][1] *= a0;
            o[nt][2] *= a1; o[nt][3] *= a1;
        }
        ls[0] *= a0; ls[1] *= a0; ls[2] *= a1; ls[3] *= a1;

#pragma unroll
        for (int js = 0; js < 4; js++) {
            const int n0 = 2 * js, n1 = 2 * js + 1;
            uint32_t pa[4];
            pa[0] = exp2_f16x2(packh2(fmaf(sc[n0][0], L2E, -mb0),
                                      fmaf(sc[n0][1], L2E, -mb0)));
            pa[1] = exp2_f16x2(packh2(fmaf(sc[n0][2], L2E, -mb1),
                                      fmaf(sc[n0][3], L2E, -mb1)));
            pa[2] = exp2_f16x2(packh2(fmaf(sc[n1][0], L2E, -mb0),
                                      fmaf(sc[n1][1], L2E, -mb0)));
            pa[3] = exp2_f16x2(packh2(fmaf(sc[n1][2], L2E, -mb1),
                                      fmaf(sc[n1][3], L2E, -mb1)));
            mma_f16(ls, pa, onesb);
#pragma unroll
            for (int p = 0; p < 4; p++) {
                const uint32_t ro = (uint32_t)((js * 16 + v_row) * AT_PITCHB
                                  + p * 32 + v_dof);
                uint32_t Bv[4];
                ldsm_x4_trans(Bv, stpu + AT_KARR + ro);
                uint32_t bv0[2] = {Bv[0], Bv[1]};
                uint32_t bv1[2] = {Bv[2], Bv[3]};
                mma_f16(o[p * 2],     pa, bv0);
                mma_f16(o[p * 2 + 1], pa, bv1);
            }
        }

        __syncthreads();
        if (kt + 2 < SEQ / 64) load_stage(kt & 1, kt + 2);
        else                   CP_COMMIT();
    }

    const float li0 = 1.f / ls[0], li1 = 1.f / ls[2];
    const int row0 = qt * 128 + wid * 16 + g;
#pragma unroll
    for (int nt = 0; nt < 8; nt++) {
        const int col = ho + nt * 8 + 2 * t;
        uint32_t h0, lo0, h1, lo1;
        packsplit2(o[nt][0] * li0, o[nt][1] * li0, h0, lo0);
        packsplit2(o[nt][2] * li1, o[nt][3] * li1, h1, lo1);
        *(uint32_t*)&g_xh[(size_t)row0 * 2048 + col]       = h0;
        *(uint32_t*)&g_xl[(size_t)row0 * 2048 + col]       = lo0;
        *(uint32_t*)&g_xh[(size_t)(row0 + 8) * 2048 + col] = h1;
        *(uint32_t*)&g_xl[(size_t)(row0 + 8) * 2048 + col] = lo1;
    }
}

// ---------------------------------------------------------------------------
// kernel_launch
// ---------------------------------------------------------------------------
extern "C" void kernel_launch(void* const* d_in, const int* in_sizes, int n_in,
                              void* d_out, int out_size)
{
    const float* query = (const float*)d_in[0];
    const float* key   = (const float*)d_in[1];
    const float* value = (const float*)d_in[2];
    const float* Wq    = (const float*)d_in[3];
    const float* bq    = (const float*)d_in[4];
    const float* Wk    = (const float*)d_in[5];
    const float* bk    = (const float*)d_in[6];
    const float* Wv    = (const float*)d_in[7];
    const float* bv    = (const float*)d_in[8];
    const float* Wo    = (const float*)d_in[9];
    const float* bo    = (const float*)d_in[10];
    float* out = (float*)d_out;

    cudaFuncSetAttribute(gemm_qkv_kernel,
                         cudaFuncAttributeMaxDynamicSharedMemorySize, G2_DSMEM);
    cudaFuncSetAttribute(gemm_o_kernel,
                         cudaFuncAttributeMaxDynamicSharedMemorySize, GK_DSMEM);
    cudaFuncSetAttribute(attn_mma_kernel,
                         cudaFuncAttributeMaxDynamicSharedMemorySize, AT_SMEM);

    // MLP=4 split: each thread handles 16 floats
    split_all_kernel<<<dim3(NTOT / 4096, 7), 256>>>(query, key, value, Wq, Wk, Wv, Wo);

    gemm_qkv_kernel<<<dim3(DIM / 128, MTOK / 128, 3), 256, G2_DSMEM>>>(bq, bk, bv);

    attn_mma_kernel<<<dim3(SEQ / 128, BATCH * NH), 256, AT_SMEM>>>();

    gemm_o_kernel<<<dim3(DIM / 128, MTOK / 128), 256, GK_DSMEM>>>(bo, out);
}